// round 2
// baseline (speedup 1.0000x reference)
#include <cuda_runtime.h>
#include <math.h>

#define Nn 131072
#define Bg 16
#define Cc 128
#define Kk 16
#define TILE 128
#define NTHREADS 256
#define XS_STRIDE 132
#define EPSF 1e-9f

// d_out layout (flattened return tuple): out[B,K,C], s[N,K], mu[B,K,2], losses[9]
#define OUT_POOL_OFF 0
#define S_OFF        (Bg*Kk*Cc)                 // 32768
#define MU_OFF       (S_OFF + Nn*Kk)            // 2129920
#define LOSS_OFF     (MU_OFF + Bg*Kk*2)         // 2130432

// scratch accumulators (no cudaMalloc allowed)
__device__ float g_sum_s[Bg*Kk];
__device__ float g_sum_pos[Bg*Kk*2];
__device__ float g_ent;

// ---------------- init ----------------
__global__ void init_kernel(float* __restrict__ out_pool) {
    int idx = blockIdx.x * blockDim.x + threadIdx.x;
    if (idx < Bg*Kk*Cc) out_pool[idx] = 0.f;
    if (blockIdx.x == 0) {
        int t = threadIdx.x;
        if (t < Bg*Kk) g_sum_s[t] = 0.f;
        for (int i = t; i < Bg*Kk*2; i += blockDim.x) g_sum_pos[i] = 0.f;
        if (t == 0) g_ent = 0.f;
    }
}

// ---------------- fused main ----------------
// smem layout (floats):
//  xs   @ 0      : TILE*XS_STRIDE (16896)   x tile, row-major stride 132
//  wh   @ 16896  : Cc*XS_STRIDE   (16896)   W1 rows, later reused as h
//  w2s  @ 33792  : Kk*Cc          (2048)
//  larr @ 35840  : TILE*17        (2176)
//  ss   @ 38016  : TILE*17        (2176)
//  psm  @ 40192  : TILE*2         (256)
//  b1s  @ 40448  : 128
//  b2s  @ 40576  : 16
//  msk  @ 40592  : 16
//  bval @ 40608  : 128 (int)
//  ent  @ 40736  : 1
#define SMEM_FLOATS 40960
#define SMEM_BYTES  (SMEM_FLOATS * 4)

extern "C" __global__ void __launch_bounds__(NTHREADS, 1)
fused_kernel(const float* __restrict__ x,
             const int* __restrict__ batch,
             const float* __restrict__ pos,
             const float* __restrict__ gumbel,
             const float* __restrict__ W1,
             const float* __restrict__ b1,
             const float* __restrict__ W2,
             const float* __restrict__ b2,
             const float* __restrict__ scaling_p,
             const float* __restrict__ amask,
             float* __restrict__ out_pool,
             float* __restrict__ s_out)
{
    extern __shared__ float sm[];
    float* xs   = sm;
    float* wh   = sm + 16896;
    float* w2s  = sm + 33792;
    float* larr = sm + 35840;
    float* ss   = sm + 38016;
    float* psm  = sm + 40192;
    float* b1s  = sm + 40448;
    float* b2s  = sm + 40576;
    float* msk  = sm + 40592;
    int*   bval = (int*)(sm + 40608);
    float* entacc = sm + 40736;

    const int tid  = threadIdx.x;
    const int base = blockIdx.x * TILE;
    const int warp = tid >> 5, lane = tid & 31;
    const float sc = __ldg(scaling_p);

    // ---- cooperative loads (coalesced float4) ----
    for (int r = warp; r < TILE; r += 8) {
        float4 v = ((const float4*)(x + (size_t)(base + r) * Cc))[lane];
        *(float4*)(xs + r * XS_STRIDE + lane * 4) = v;
    }
    for (int r = warp; r < Cc; r += 8) {
        float4 v = ((const float4*)(W1 + (size_t)r * Cc))[lane];
        *(float4*)(wh + r * XS_STRIDE + lane * 4) = v;
    }
    for (int r = warp; r < Kk; r += 8) {
        float4 v = ((const float4*)(W2 + (size_t)r * Cc))[lane];
        *(float4*)(w2s + r * Cc + lane * 4) = v;
    }
    if (tid < Cc) b1s[tid] = b1[tid];
    if (tid < Kk) { b2s[tid] = b2[tid]; msk[tid] = amask[tid]; }
    if (tid < TILE) {
        int bv = batch[base + tid];          // int32 (JAX x64 disabled)
        bval[tid] = bv < 0 ? 0 : (bv >= Bg ? Bg - 1 : bv);
        psm[tid*2]   = pos[(size_t)(base + tid)*2];
        psm[tid*2+1] = pos[(size_t)(base + tid)*2 + 1];
    }
    if (tid == 0) entacc[0] = 0.f;
    __syncthreads();

    // ---- GEMM: h[128 nodes][128 cols], 8x8 register tile per thread ----
    const int tx = tid & 15, ty = tid >> 4;
    float h[8][8];
    #pragma unroll
    for (int i = 0; i < 8; i++)
        #pragma unroll
        for (int j = 0; j < 8; j++) h[i][j] = 0.f;

    #pragma unroll 4
    for (int k = 0; k < Cc; ++k) {
        float a[8], bb[8];
        #pragma unroll
        for (int i = 0; i < 8; i++) a[i]  = xs[(ty + 16*i) * XS_STRIDE + k];
        #pragma unroll
        for (int j = 0; j < 8; j++) bb[j] = wh[(tx + 16*j) * XS_STRIDE + k];
        #pragma unroll
        for (int i = 0; i < 8; i++)
            #pragma unroll
            for (int j = 0; j < 8; j++) h[i][j] += a[i] * bb[j];
    }
    __syncthreads();   // everyone done reading W1 before overwriting wh with h

    // epilogue: relu(+b1) -> hs (reusing wh region)
    #pragma unroll
    for (int j = 0; j < 8; j++) {
        float bj = b1s[tx + 16*j];
        #pragma unroll
        for (int i = 0; i < 8; i++) {
            float v = h[i][j] + bj;
            wh[(ty + 16*i) * XS_STRIDE + (tx + 16*j)] = v > 0.f ? v : 0.f;
        }
    }
    __syncthreads();

    // ---- logits: [128 nodes][16], each thread does 8 k's for one node ----
    {
        const int n  = tid & 127;
        const int kg = tid >> 7;   // 0 or 1 -> k base 0 / 8
        float lacc[8];
        #pragma unroll
        for (int kk = 0; kk < 8; kk++) lacc[kk] = b2s[kg*8 + kk];
        for (int j = 0; j < Cc; j++) {
            float hv = wh[n * XS_STRIDE + j];
            #pragma unroll
            for (int kk = 0; kk < 8; kk++)
                lacc[kk] += hv * w2s[(kg*8 + kk) * Cc + j];
        }
        #pragma unroll
        for (int kk = 0; kk < 8; kk++)
            larr[n*17 + kg*8 + kk] = lacc[kk] * sc;
    }
    __syncthreads();

    // ---- gumbel softmax + entropy + s output (128 threads, one node each) ----
    if (tid < TILE) {
        const int n = tid;
        float gv[16];
        const float4* gp = (const float4*)(gumbel + (size_t)(base + n) * Kk);
        #pragma unroll
        for (int q = 0; q < 4; q++) {
            float4 g = gp[q];
            gv[q*4+0]=g.x; gv[q*4+1]=g.y; gv[q*4+2]=g.z; gv[q*4+3]=g.w;
        }
        float z[16];
        float mx = -3.4e38f;
        #pragma unroll
        for (int k = 0; k < Kk; k++) {
            float l = larr[n*17 + k];
            if (msk[k] == 0.f) l = -1e9f;
            z[k] = l + gv[k];            // TAU = 1.0
            mx = fmaxf(mx, z[k]);
        }
        float sum = 0.f;
        #pragma unroll
        for (int k = 0; k < Kk; k++) { z[k] = __expf(z[k] - mx); sum += z[k]; }
        float inv = 1.f / sum;
        float ent = 0.f;
        float so[16];
        #pragma unroll
        for (int k = 0; k < Kk; k++) {
            float sv = z[k] * inv;
            ss[n*17 + k] = sv;
            so[k] = sv;
            ent += sv * __logf(sv + EPSF);
        }
        float4* sp = (float4*)(s_out + (size_t)(base + n) * Kk);
        #pragma unroll
        for (int q = 0; q < 4; q++)
            sp[q] = make_float4(so[q*4], so[q*4+1], so[q*4+2], so[q*4+3]);
        atomicAdd(entacc, ent);
    }
    __syncthreads();
    if (tid == 0) atomicAdd(&g_ent, entacc[0]);

    // ---- pooling: batch is sorted -> block spans contiguous segment ids ----
    {
        const int b_lo = bval[0], b_hi = bval[TILE-1];
        const int kk = tid >> 4;        // 0..15
        const int c0 = tid & 15;        // c = c0 + 16*q
        for (int b = b_lo; b <= b_hi; ++b) {
            float racc[8];
            #pragma unroll
            for (int q = 0; q < 8; q++) racc[q] = 0.f;
            float ssum = 0.f, p0 = 0.f, p1 = 0.f;
            for (int n = 0; n < TILE; n++) {
                if (bval[n] == b) {
                    float sv = ss[n*17 + kk];
                    #pragma unroll
                    for (int q = 0; q < 8; q++)
                        racc[q] += sv * xs[n * XS_STRIDE + c0 + 16*q];
                    if (c0 == 0) {
                        ssum += sv;
                        p0 += sv * psm[n*2];
                        p1 += sv * psm[n*2+1];
                    }
                }
            }
            float* op = out_pool + ((size_t)(b*Kk + kk)) * Cc;
            #pragma unroll
            for (int q = 0; q < 8; q++) atomicAdd(op + c0 + 16*q, racc[q]);
            if (c0 == 0) {
                atomicAdd(&g_sum_s[b*Kk + kk], ssum);
                atomicAdd(&g_sum_pos[(b*Kk + kk)*2],     p0);
                atomicAdd(&g_sum_pos[(b*Kk + kk)*2 + 1], p1);
            }
        }
    }
}

// ---------------- finalize ----------------
__global__ void finalize_kernel(const float* __restrict__ amask,
                                float* __restrict__ out)
{
    __shared__ float avg[Kk];
    __shared__ float mu_s[Bg*Kk*2];
    __shared__ float sepacc;
    const int tid = threadIdx.x;
    if (tid == 0) sepacc = 0.f;
    if (tid < Kk) {
        float s = 0.f;
        for (int b = 0; b < Bg; b++) s += g_sum_s[b*Kk + tid];
        avg[tid] = s / (float)Nn;
    }
    for (int i = tid; i < Bg*Kk*2; i += blockDim.x) {
        int bk = i >> 1;
        float m = g_sum_pos[i] / (g_sum_s[bk] + EPSF);
        mu_s[i] = m;
        out[MU_OFF + i] = m;
    }
    __syncthreads();

    // separation: sum over b of off-diagonal 1/(d^2+1), / (K*(K-1))
    float rep = 0.f;
    for (int i = tid; i < Bg*Kk*Kk; i += blockDim.x) {
        int b = i >> 8, r = i & 255, j = r >> 4, k = r & 15;
        if (j != k) {
            float dx = mu_s[(b*Kk + j)*2]     - mu_s[(b*Kk + k)*2];
            float dy = mu_s[(b*Kk + j)*2 + 1] - mu_s[(b*Kk + k)*2 + 1];
            rep += 1.f / (dx*dx + dy*dy + 1.f);
        }
    }
    #pragma unroll
    for (int off = 16; off; off >>= 1) rep += __shfl_down_sync(0xffffffffu, rep, off);
    if ((tid & 31) == 0) atomicAdd(&sepacc, rep);
    __syncthreads();

    if (tid == 0) {
        const float up = 1.f / (float)Kk;
        float entropy = -g_ent / (float)Nn;
        float div = 0.f, prun = 0.f, msum = 0.f, col = 0.f, mean = 0.f;
        for (int k = 0; k < Kk; k++) {
            div  += up * logf(up / (avg[k] + EPSF));
            prun += fabsf(avg[k] * (1.f - amask[k]));
            msum += amask[k];
            float d = avg[k] - up;
            col  += d * d;
            mean += avg[k];
        }
        prun /= (float)Kk;
        float sparsity = (msum / (float)Kk) * 0.01f;
        col *= 2.0f;
        mean /= (float)Kk;
        float var = 0.f;
        for (int k = 0; k < Kk; k++) { float d = avg[k] - mean; var += d * d; }
        var /= (float)Kk;
        float bal = sqrtf(var);
        float sep = sepacc / (float)(Kk * (Kk - 1));
        float* L = out + LOSS_OFF;
        L[0] = entropy; L[1] = div; L[2] = 0.f; L[3] = prun; L[4] = sparsity;
        L[5] = 0.f;     L[6] = col; L[7] = bal; L[8] = sep;
    }
}

extern "C" void kernel_launch(void* const* d_in, const int* in_sizes, int n_in,
                              void* d_out, int out_size)
{
    const float* x     = (const float*)d_in[0];
    const int*   batch = (const int*)d_in[1];
    const float* pos   = (const float*)d_in[2];
    const float* gum   = (const float*)d_in[3];
    const float* W1    = (const float*)d_in[4];
    const float* b1    = (const float*)d_in[5];
    const float* W2    = (const float*)d_in[6];
    const float* b2    = (const float*)d_in[7];
    const float* scal  = (const float*)d_in[8];
    const float* amask = (const float*)d_in[9];
    float* out = (float*)d_out;

    static bool attr_set = false;
    if (!attr_set) {
        cudaFuncSetAttribute(fused_kernel,
                             cudaFuncAttributeMaxDynamicSharedMemorySize, SMEM_BYTES);
        attr_set = true;
    }

    init_kernel<<<(Bg*Kk*Cc + NTHREADS - 1)/NTHREADS, NTHREADS>>>(out + OUT_POOL_OFF);
    fused_kernel<<<Nn / TILE, NTHREADS, SMEM_BYTES>>>(
        x, batch, pos, gum, W1, b1, W2, b2, scal, amask,
        out + OUT_POOL_OFF, out + S_OFF);
    finalize_kernel<<<1, NTHREADS>>>(amask, out);
}